// round 9
// baseline (speedup 1.0000x reference)
#include <cuda_runtime.h>
#include <cstdint>
#include <math.h>

// ---------------------------------------------------------------------------
// NeuralODE Tsit5 — persistent-CTA fp32 kernel, round 8.
// No split-K: 16 warps x (16 exclusive cols x all 32 rows).
// W pre-duplicated in SMEM tiles -> k-loop has ZERO movs:
//   per warp-k: 1 LDS.128 (A packed row-pairs) + 2 LDS.128 (W dup pairs)
//               + 8 ffma2   (11 instr, 3 crossbar-cyc)
// Double-buffered dup-W tiles filled via LDG.64 -> STS.128 (bank-clean).
// ---------------------------------------------------------------------------

#define BATCH   4096
#define DIM     64
#define WIDTH   256
#define NTT     101
#define TM      32
#define NCTA    (BATCH / TM)      // 128
#define THREADS 512

// row swizzle: element r of feature-row n lives at slot r ^ SWR(n) (mult of 4)
#define SWR(idx) ((((idx) >> 3) & 7) << 2)

#define ACT_SIZE  (WIDTH * TM)    // 8192 floats
#define ZK_SIZE   (DIM * TM)      // 2048 floats
#define WTILE_F   16384           // 64KB dup tile (32 rows x 512 | 128 rows x 128)

#define SMEM_FLOATS (ACT_SIZE + 2*WTILE_F + ZK_SIZE + ZK_SIZE + 6*ZK_SIZE)
#define SMEM_BYTES  (SMEM_FLOATS * 4)   // 224KB

// Tsit5 tableau
__constant__ float c_A[6][5] = {
    {0.f, 0.f, 0.f, 0.f, 0.f},
    {0.161f, 0.f, 0.f, 0.f, 0.f},
    {-0.008480655492356989f, 0.335480655492357f, 0.f, 0.f, 0.f},
    {2.8971530571054935f, -6.359448489975075f, 4.3622954328695815f, 0.f, 0.f},
    {5.325864828439257f, -11.748883564062828f, 7.4955393428898365f, -0.09249506636175525f, 0.f},
    {5.86145544294642f, -12.92096931784711f, 8.159367898576159f, -0.071584973281401f, -0.028269050394068383f}
};
__constant__ float c_B[6] = {
    0.09646076681806523f, 0.01f, 0.4798896504144996f,
    1.379008574103742f, -3.290069515436081f, 2.324710524099774f
};

// ---- packed f32x2 helpers ----
__device__ __forceinline__ unsigned long long pk2(float lo, float hi) {
    unsigned long long r;
    asm("mov.b64 %0, {%1, %2};" : "=l"(r) : "f"(lo), "f"(hi));
    return r;
}
__device__ __forceinline__ void upk2(unsigned long long v, float &lo, float &hi) {
    asm("mov.b64 {%0, %1}, %2;" : "=f"(lo), "=f"(hi) : "l"(v));
}
__device__ __forceinline__ void ffma2(unsigned long long &d,
                                      unsigned long long a,
                                      unsigned long long b) {
    asm("fma.rn.f32x2 %0, %1, %2, %0;" : "+l"(d) : "l"(a), "l"(b));
}

// ---------------------------------------------------------------------------
// Fill a dup-W tile (N=256): 32 source rows -> [32][512] dup layout.
// Unit = one source float2 -> one 16B dup chunk (x,x,y,y). Bank-clean STS.128.
// ---------------------------------------------------------------------------
__device__ __forceinline__ void fill256(float *dst, const float *__restrict__ Wg, int t) {
    const float2 *src = reinterpret_cast<const float2 *>(Wg) + (size_t)t * 32 * 128;
#pragma unroll
    for (int u = 0; u < 8; u++) {
        int m   = threadIdx.x + u * THREADS;   // 0..4095
        int row = m >> 7;                      // 0..31
        int j2  = m & 127;
        float2 s = __ldg(src + row * 128 + j2);
        float4 d; d.x = s.x; d.y = s.x; d.z = s.y; d.w = s.y;
        *reinterpret_cast<float4 *>(dst + row * 512 + 4 * j2) = d;
    }
}

// Fill a dup-W tile (N=64): 128 source rows -> [128][128] dup layout.
__device__ __forceinline__ void fill64(float *dst, const float *__restrict__ Wg, int t) {
    const float2 *src = reinterpret_cast<const float2 *>(Wg) + (size_t)t * 128 * 32;
#pragma unroll
    for (int u = 0; u < 8; u++) {
        int m   = threadIdx.x + u * THREADS;   // 0..4095
        int row = m >> 5;                      // 0..127
        int j2  = m & 31;
        float2 s = __ldg(src + row * 32 + j2);
        float4 d; d.x = s.x; d.y = s.x; d.z = s.y; d.w = s.y;
        *reinterpret_cast<float4 *>(dst + row * 128 + 4 * j2) = d;
    }
}

// ---------------------------------------------------------------------------
// Layer with N=256 output: Aout[c][r^SWR(c)] = act( sum_k W[k][c]*Ain[k][r^SWR(k)] + b[c] )
// warp w owns cols [16w,16w+16); lane: rows 4*(lane&7)..+3, cols +4*(lane>>3).
// In-place (Aout==Ain) safe: sync after k-loop, then epilogue, then sync.
// ---------------------------------------------------------------------------
template <int K, bool ACT>
__device__ __forceinline__ void layer256(const float *Ain, float *Aout,
                                         const float *__restrict__ Wg,
                                         const float *__restrict__ bg,
                                         float *wbuf) {
    constexpr int TILES = K / 32;
    const int tid  = threadIdx.x;
    const int w    = tid >> 5;
    const int lane = tid & 31;
    const int r0   = 4 * (lane & 7);
    const int c0   = 16 * w + 4 * (lane >> 3);

    unsigned long long acc[2][4];
#pragma unroll
    for (int c = 0; c < 4; c++) {
        float b = __ldg(bg + c0 + c);
        unsigned long long bb = pk2(b, b);
        acc[0][c] = bb;
        acc[1][c] = bb;
    }

    fill256(wbuf, Wg, 0);
    __syncthreads();

    for (int t = 0; t < TILES; ++t) {
        if (t + 1 < TILES)
            fill256(wbuf + ((t + 1) & 1) * WTILE_F, Wg, t + 1);

        const float *wt = wbuf + (t & 1) * WTILE_F + 2 * c0;
#pragma unroll
        for (int g = 0; g < 4; ++g) {
            const int kbase = t * 32 + g * 8;
            const int swk   = SWR(kbase);
            const float *ap = Ain + kbase * TM + (r0 ^ swk);
            const float *wp = wt + g * 8 * 512;
#pragma unroll
            for (int kk = 0; kk < 8; ++kk) {
                ulonglong2 A  = *reinterpret_cast<const ulonglong2 *>(ap + kk * TM);
                ulonglong2 Wa = *reinterpret_cast<const ulonglong2 *>(wp + kk * 512);
                ulonglong2 Wb = *reinterpret_cast<const ulonglong2 *>(wp + kk * 512 + 4);
                ffma2(acc[0][0], A.x, Wa.x); ffma2(acc[1][0], A.y, Wa.x);
                ffma2(acc[0][1], A.x, Wa.y); ffma2(acc[1][1], A.y, Wa.y);
                ffma2(acc[0][2], A.x, Wb.x); ffma2(acc[1][2], A.y, Wb.x);
                ffma2(acc[0][3], A.x, Wb.y); ffma2(acc[1][3], A.y, Wb.y);
            }
        }
        __syncthreads();
    }

    // epilogue (all k-loop reads done at last sync)
#pragma unroll
    for (int c = 0; c < 4; c++) {
        float x0, x1, x2, x3;
        upk2(acc[0][c], x0, x1);
        upk2(acc[1][c], x2, x3);
        if (ACT) { x0 = tanhf(x0); x1 = tanhf(x1); x2 = tanhf(x2); x3 = tanhf(x3); }
        float4 v; v.x = x0; v.y = x1; v.z = x2; v.w = x3;
        const int cc = c0 + c;
        *reinterpret_cast<float4 *>(Aout + cc * TM + (r0 ^ SWR(cc))) = v;
    }
    __syncthreads();
}

// ---------------------------------------------------------------------------
// Layer with N=64 output (K=256): no activation (produces k-stage).
// warp w owns cols [4w,4w+4); lane: rows 2*(lane&15), cols 4w+2*(lane>>4).
// ---------------------------------------------------------------------------
__device__ __forceinline__ void layer64(const float *Ain, float *Aout,
                                        const float *__restrict__ Wg,
                                        const float *__restrict__ bg,
                                        float *wbuf) {
    const int tid  = threadIdx.x;
    const int w    = tid >> 5;
    const int lane = tid & 31;
    const int r0   = 2 * (lane & 15);
    const int c0   = 4 * w + 2 * (lane >> 4);

    unsigned long long acc[2];
    acc[0] = pk2(__ldg(bg + c0),     __ldg(bg + c0));
    acc[1] = pk2(__ldg(bg + c0 + 1), __ldg(bg + c0 + 1));

    fill64(wbuf, Wg, 0);
    __syncthreads();

    for (int t = 0; t < 2; ++t) {
        if (t == 0)
            fill64(wbuf + WTILE_F, Wg, 1);

        const float *wt = wbuf + t * WTILE_F + 2 * c0;
#pragma unroll
        for (int g = 0; g < 16; ++g) {
            const int kbase = t * 128 + g * 8;
            const int swk   = SWR(kbase);
            const float *ap = Ain + kbase * TM + (r0 ^ swk);
            const float *wp = wt + g * 8 * 128;
#pragma unroll
            for (int kk = 0; kk < 8; ++kk) {
                unsigned long long A = *reinterpret_cast<const unsigned long long *>(ap + kk * TM);
                ulonglong2 Wv = *reinterpret_cast<const ulonglong2 *>(wp + kk * 128);
                ffma2(acc[0], A, Wv.x);
                ffma2(acc[1], A, Wv.y);
            }
        }
        __syncthreads();
    }

#pragma unroll
    for (int c = 0; c < 2; c++) {
        float x0, x1;
        upk2(acc[c], x0, x1);
        float2 v; v.x = x0; v.y = x1;
        const int cc = c0 + c;
        *reinterpret_cast<float2 *>(Aout + cc * TM + (r0 ^ SWR(cc))) = v;
    }
    __syncthreads();
}

// ---------------------------------------------------------------------------
__global__ void __launch_bounds__(THREADS, 1)
node_kernel(const float *__restrict__ ts, const float *__restrict__ y0,
            const float *__restrict__ W0, const float *__restrict__ b0,
            const float *__restrict__ W1, const float *__restrict__ b1,
            const float *__restrict__ W2, const float *__restrict__ b2,
            const float *__restrict__ W3, const float *__restrict__ b3,
            float *__restrict__ out) {
    extern __shared__ float sm[];
    float *act  = sm;                    // 8192  [256][32] row-swizzled
    float *wbuf = act + ACT_SIZE;        // 32768 (2 x 64KB dup tiles)
    float *zbuf = wbuf + 2 * WTILE_F;    // 2048  [64][32] row-swizzled
    float *ybuf = zbuf + ZK_SIZE;        // 2048
    float *kbuf = ybuf + ZK_SIZE;        // 6 x 2048

    const int tid = threadIdx.x;
    const int cta = blockIdx.x;

    // ingest y0 (row-major) -> ybuf (transposed, row-swizzled); emit out[0]
    {
        const float *y0c = y0 + (size_t)cta * TM * DIM;
        float *o0 = out + (size_t)cta * TM * DIM;
        for (int i = tid; i < TM * DIM; i += THREADS) {
            const int r = i >> 6;
            const int d = i & 63;
            float v = __ldg(y0c + i);
            ybuf[d * TM + (r ^ SWR(d))] = v;
            o0[i] = v;
        }
    }
    __syncthreads();

    for (int t = 1; t < NTT; ++t) {
        const float h = __ldg(ts + t) - __ldg(ts + t - 1);

        for (int s = 0; s < 6; ++s) {
            const float *zin;
            if (s == 0) {
                zin = ybuf;
            } else {
                // z = y + h * sum_{j<s} A[s][j]*k_j (elementwise, same layout)
                float4 *zb = reinterpret_cast<float4 *>(zbuf);
                const float4 *yb = reinterpret_cast<const float4 *>(ybuf);
                for (int i = tid; i < ZK_SIZE / 4; i += THREADS) {
                    float4 v = yb[i];
                    for (int j = 0; j < s; j++) {
                        float c = h * c_A[s][j];
                        float4 kv = reinterpret_cast<const float4 *>(kbuf + j * ZK_SIZE)[i];
                        v.x += c * kv.x; v.y += c * kv.y;
                        v.z += c * kv.z; v.w += c * kv.w;
                    }
                    zb[i] = v;
                }
                __syncthreads();
                zin = zbuf;
            }

            layer256<DIM,   true>(zin, act, W0, b0, wbuf);
            layer256<WIDTH, true>(act, act, W1, b1, wbuf);
            layer256<WIDTH, true>(act, act, W2, b2, wbuf);
            layer64              (act, kbuf + s * ZK_SIZE, W3, b3, wbuf);
        }

        // y += h * sum_j B[j]*k_j (elementwise)
        {
            float4 *yb = reinterpret_cast<float4 *>(ybuf);
            for (int i = tid; i < ZK_SIZE / 4; i += THREADS) {
                float4 v = yb[i];
#pragma unroll
                for (int j = 0; j < 6; j++) {
                    float c = h * c_B[j];
                    float4 kv = reinterpret_cast<const float4 *>(kbuf + j * ZK_SIZE)[i];
                    v.x += c * kv.x; v.y += c * kv.y;
                    v.z += c * kv.z; v.w += c * kv.w;
                }
                yb[i] = v;
            }
        }
        __syncthreads();

        // store out[t] (row-major, coalesced) from swizzled ybuf
        {
            float *outc = out + (size_t)t * (BATCH * DIM) + (size_t)cta * TM * DIM;
            for (int i = tid; i < TM * DIM; i += THREADS) {
                const int r = i >> 6;
                const int d = i & 63;
                outc[i] = ybuf[d * TM + (r ^ SWR(d))];
            }
        }
        __syncthreads();
    }
}

// ---------------------------------------------------------------------------
extern "C" void kernel_launch(void *const *d_in, const int *in_sizes, int n_in,
                              void *d_out, int out_size) {
    const float *ts = (const float *)d_in[0];
    const float *y0 = (const float *)d_in[1];
    const float *W0 = (const float *)d_in[2];
    const float *b0 = (const float *)d_in[3];
    const float *W1 = (const float *)d_in[4];
    const float *b1 = (const float *)d_in[5];
    const float *W2 = (const float *)d_in[6];
    const float *b2 = (const float *)d_in[7];
    const float *W3 = (const float *)d_in[8];
    const float *b3 = (const float *)d_in[9];
    float *out = (float *)d_out;

    cudaFuncSetAttribute(node_kernel,
                         cudaFuncAttributeMaxDynamicSharedMemorySize, SMEM_BYTES);
    node_kernel<<<NCTA, THREADS, SMEM_BYTES>>>(ts, y0, W0, b0, W1, b1,
                                               W2, b2, W3, b3, out);
}